// round 14
// baseline (speedup 1.0000x reference)
#include <cuda_runtime.h>
#include <cuda_fp16.h>

#define N_ROWS 65536
#define EDIM 512
#define NE 1024
#define VQ_DEPTH 6
#define MARGIN 2.5e-4f

// Scratch (static __device__ globals: allocation-free per harness rules)
__device__ float g_zf[(size_t)N_ROWS * EDIM];            // 128 MB unfolded (fp32, exact)
__device__ __half g_zf_h[(size_t)N_ROWS * EDIM];         // 64 MB  fp16 copy for MMA
__device__ __half g_emb_h[NE * EDIM];                    // 1 MB
__device__ float g_u[(size_t)N_ROWS * NE];               // 256 MB u0 = 2 r.e (approx ok)
__device__ float g_G2[NE * NE];                          // 4 MB   2 E E^T (approx ok)
__device__ float g_esq[NE];
__device__ float g_partial[N_ROWS];

// ---------------------------------------------------------------------------
// unfold: zf[n][d] = x[b][c][2hb+ki][2wb+kj]; also emit fp16 copy for MMA.
// ---------------------------------------------------------------------------
__global__ void unfold_kernel(const float* __restrict__ x) {
    int bid = blockIdx.x;
    int b = bid >> 14, c = (bid >> 7) & 127, hb = bid & 127;
    int wb = threadIdx.x;
    const float* xr = x + (((long)((b << 7) + c)) << 16) + ((long)(hb << 1) << 8);
    float2 r0 = *(const float2*)(xr + wb * 2);
    float2 r1 = *(const float2*)(xr + 256 + wb * 2);
    long n = ((long)((b << 7) + hb) << 7) + wb;
    float4 v; v.x = r0.x; v.y = r0.y; v.z = r1.x; v.w = r1.y;
    *(float4*)(g_zf + n * EDIM + c * 4) = v;
    __half2 p0, p1;
    p0.x = __float2half_rn(v.x); p0.y = __float2half_rn(v.y);
    p1.x = __float2half_rn(v.z); p1.y = __float2half_rn(v.w);
    *(__half2*)(g_zf_h + n * EDIM + c * 4)     = p0;
    *(__half2*)(g_zf_h + n * EDIM + c * 4 + 2) = p1;
}

// ---------------------------------------------------------------------------
// emb_prep: fused gram (blocks 0..255) + esq (blocks 256..383) +
// emb->fp16 (blocks 384..447).
// ---------------------------------------------------------------------------
__global__ __launch_bounds__(256) void emb_prep_kernel(const float* __restrict__ emb) {
    __shared__ float As[16][64];
    __shared__ float Bs[16][64];
    int blk = blockIdx.x;
    int tid = threadIdx.x;

    if (blk < 256) {
        int row0 = (blk >> 4) * 64;
        int col0 = (blk & 15) * 64;
        int tx = tid & 15, ty = tid >> 4;
        float acc[4][4];
#pragma unroll
        for (int i = 0; i < 4; i++)
#pragma unroll
            for (int j = 0; j < 4; j++) acc[i][j] = 0.f;
        const float* Ab = emb + (long)row0 * 512;
        const float* Bb = emb + (long)col0 * 512;
        int r0 = tid >> 2, c4 = tid & 3;
        for (int k0 = 0; k0 < 512; k0 += 16) {
            float4 va = *(const float4*)(Ab + (long)r0 * 512 + k0 + c4 * 4);
            As[c4 * 4 + 0][r0] = va.x; As[c4 * 4 + 1][r0] = va.y;
            As[c4 * 4 + 2][r0] = va.z; As[c4 * 4 + 3][r0] = va.w;
            float4 vb = *(const float4*)(Bb + (long)r0 * 512 + k0 + c4 * 4);
            Bs[c4 * 4 + 0][r0] = vb.x; Bs[c4 * 4 + 1][r0] = vb.y;
            Bs[c4 * 4 + 2][r0] = vb.z; Bs[c4 * 4 + 3][r0] = vb.w;
            __syncthreads();
#pragma unroll
            for (int kk = 0; kk < 16; kk++) {
                float ra[4], rb[4];
                *(float4*)ra = *(const float4*)&As[kk][ty * 4];
                *(float4*)rb = *(const float4*)&Bs[kk][tx * 4];
#pragma unroll
                for (int i = 0; i < 4; i++)
#pragma unroll
                    for (int j = 0; j < 4; j++) acc[i][j] += ra[i] * rb[j];
            }
            __syncthreads();
        }
#pragma unroll
        for (int i = 0; i < 4; i++) {
            long r = row0 + ty * 4 + i;
            float4 v;
            v.x = 2.f * acc[i][0]; v.y = 2.f * acc[i][1];
            v.z = 2.f * acc[i][2]; v.w = 2.f * acc[i][3];
            *(float4*)(g_G2 + r * NE + col0 + tx * 4) = v;
        }
    } else if (blk < 384) {
        int w = (blk - 256) * 8 + (tid >> 5);
        int lane = tid & 31;
        const float* e = emb + (long)w * EDIM;
        float acc = 0.f;
        for (int i = lane; i < EDIM; i += 32)
            acc = __fadd_rn(acc, __fmul_rn(e[i], e[i]));
        for (int off = 16; off; off >>= 1)
            acc = __fadd_rn(acc, __shfl_down_sync(0xffffffffu, acc, off));
        if (lane == 0) g_esq[w] = acc;
    } else {
        for (int i = (blk - 384) * 256 + tid; i < NE * EDIM; i += 64 * 256)
            g_emb_h[i] = __float2half_rn(emb[i]);
    }
}

// ---------------------------------------------------------------------------
// Tensor-core GEMM (fp16 operands, fp32 accum): g_u = 2 * zf_h @ emb_h^T.
// Tile 128x128x32, 4-stage cp.async.
// ---------------------------------------------------------------------------
#define SMSTRIDE 40

__device__ __forceinline__ unsigned smaddr(const void* p) {
    return (unsigned)__cvta_generic_to_shared(p);
}
#define CP16(dst, src) \
    asm volatile("cp.async.cg.shared.global [%0], [%1], 16;" :: "r"(dst), "l"(src))

__device__ __forceinline__ void mma16816(float* c, const unsigned* a,
                                         unsigned b0, unsigned b1) {
    asm volatile(
        "mma.sync.aligned.m16n8k16.row.col.f32.f16.f16.f32 "
        "{%0,%1,%2,%3}, {%4,%5,%6,%7}, {%8,%9}, {%0,%1,%2,%3};"
        : "+f"(c[0]), "+f"(c[1]), "+f"(c[2]), "+f"(c[3])
        : "r"(a[0]), "r"(a[1]), "r"(a[2]), "r"(a[3]), "r"(b0), "r"(b1));
}

__global__ __launch_bounds__(256) void gemm_u_mma(void) {
    __shared__ __half sA[4][128 * SMSTRIDE];
    __shared__ __half sB[4][128 * SMSTRIDE];
    int tid = threadIdx.x;
    int wid = tid >> 5, lane = tid & 31;
    int warp_m = wid & 3, warp_n = wid >> 2;
    long row0 = (long)blockIdx.y * 128;
    int  col0 = blockIdx.x * 128;

    const __half* Ag = g_zf_h + row0 * 512;
    const __half* Bg = g_emb_h + (long)col0 * 512;

    int lrow = tid >> 2, lchk = tid & 3;

    float acc[2][8][4];
#pragma unroll
    for (int i = 0; i < 2; i++)
#pragma unroll
        for (int j = 0; j < 8; j++)
#pragma unroll
            for (int q = 0; q < 4; q++) acc[i][j][q] = 0.f;

#define STAGE_LOAD(st, k0)                                                      \
    {                                                                           \
        _Pragma("unroll")                                                       \
        for (int h = 0; h < 2; h++) {                                           \
            int r = lrow + h * 64;                                              \
            CP16(smaddr(&sA[st][r * SMSTRIDE + lchk * 8]),                      \
                 Ag + (long)r * 512 + (k0) + lchk * 8);                         \
            CP16(smaddr(&sB[st][r * SMSTRIDE + lchk * 8]),                      \
                 Bg + (long)r * 512 + (k0) + lchk * 8);                         \
        }                                                                       \
        asm volatile("cp.async.commit_group;");                                 \
    }

    STAGE_LOAD(0, 0);
    STAGE_LOAD(1, 32);
    STAGE_LOAD(2, 64);

    int lr8 = (lane & 7) + ((lane >> 3) & 1) * 8;
    int lc8 = ((lane >> 4) & 1) * 8;

#pragma unroll 1
    for (int it = 0; it < 16; it++) {
        asm volatile("cp.async.wait_group 2;" ::: "memory");
        __syncthreads();
        if (it + 3 < 16) STAGE_LOAD((it + 3) & 3, (it + 3) * 32);
        int st = it & 3;
#pragma unroll
        for (int ks = 0; ks < 2; ks++) {
            unsigned a[2][4];
#pragma unroll
            for (int mt = 0; mt < 2; mt++) {
                unsigned ad = smaddr(&sA[st][(warp_m * 32 + mt * 16 + lr8) * SMSTRIDE
                                             + ks * 16 + lc8]);
                asm volatile("ldmatrix.sync.aligned.m8n8.x4.shared.b16 "
                             "{%0,%1,%2,%3}, [%4];"
                             : "=r"(a[mt][0]), "=r"(a[mt][1]),
                               "=r"(a[mt][2]), "=r"(a[mt][3]) : "r"(ad));
            }
#pragma unroll
            for (int g = 0; g < 4; g++) {
                unsigned r0, r1, r2, r3;
                unsigned bd = smaddr(&sB[st][(warp_n * 64 + g * 16 + lr8) * SMSTRIDE
                                             + ks * 16 + lc8]);
                asm volatile("ldmatrix.sync.aligned.m8n8.x4.shared.b16 "
                             "{%0,%1,%2,%3}, [%4];"
                             : "=r"(r0), "=r"(r1), "=r"(r2), "=r"(r3) : "r"(bd));
#pragma unroll
                for (int mt = 0; mt < 2; mt++) {
                    mma16816(acc[mt][g * 2 + 0], a[mt], r0, r2);
                    mma16816(acc[mt][g * 2 + 1], a[mt], r1, r3);
                }
            }
        }
    }

#pragma unroll
    for (int mt = 0; mt < 2; mt++) {
#pragma unroll
        for (int nt = 0; nt < 8; nt++) {
            long m = row0 + warp_m * 32 + mt * 16 + (lane >> 2);
            int  n = col0 + warp_n * 64 + nt * 8 + (lane & 3) * 2;
            float2 v0, v1;
            v0.x = 2.f * acc[mt][nt][0]; v0.y = 2.f * acc[mt][nt][1];
            v1.x = 2.f * acc[mt][nt][2]; v1.y = 2.f * acc[mt][nt][3];
            *(float2*)(g_u + m * NE + n)       = v0;
            *(float2*)(g_u + (m + 8) * NE + n) = v1;
        }
    }
}

// ---------------------------------------------------------------------------
// VQ: one warp per row, deterministic.
// Fast path: s_j = esq_j - u_j register-resident; min via redux.sync;
// census via ballots. Refine (rare): candidates staged 2-at-a-time into
// padded smem (stride 513 -> conflict-free LDS), coalesced global loads;
// chains keep exact sequential-k FFMA order (shfl rr broadcast + LDS).
// ---------------------------------------------------------------------------
__global__ __launch_bounds__(128, 8) void vq_kernel(const float* __restrict__ emb,
                                                    float* __restrict__ out) {
    __shared__ float s_stage[4][2][513];
    int wid = threadIdx.x >> 5, lane = threadIdx.x & 31;
    int n = blockIdx.x * 4 + wid;

    float4 s4[8];
    {
        const float4* gu4 = (const float4*)(g_u + (long)n * NE);
        const float4* ge4 = (const float4*)g_esq;
#pragma unroll
        for (int q = 0; q < 8; q++) {
            float4 u = gu4[lane + 32 * q];
            float4 e = ge4[lane + 32 * q];
            s4[q].x = __fsub_rn(e.x, u.x);
            s4[q].y = __fsub_rn(e.y, u.y);
            s4[q].z = __fsub_rn(e.z, u.z);
            s4[q].w = __fsub_rn(e.w, u.w);
        }
    }

    int idxs[VQ_DEPTH];
#pragma unroll 1
    for (int t = 0; t < VQ_DEPTH; t++) {
        // lane-local min over 32 scores
        float m01, m23, mloc = 3.4e38f;
#pragma unroll
        for (int q = 0; q < 8; q++) {
            m01 = fminf(s4[q].x, s4[q].y);
            m23 = fminf(s4[q].z, s4[q].w);
            mloc = fminf(mloc, fminf(m01, m23));
        }
        // warp min via redux on monotonic uint mapping
        unsigned k = __float_as_uint(mloc);
        k = k ^ (unsigned)(((int)k >> 31) | 0x80000000);
        unsigned km;
        asm("redux.sync.min.u32 %0, %1, 0xffffffff;" : "=r"(km) : "r"(k));
        unsigned ub = (km & 0x80000000u) ? (km ^ 0x80000000u) : ~km;
        float thr = __uint_as_float(ub) + MARGIN;

        // candidate bitmask per lane (bit = q*4+r for j = 4*lane+128*q+r)
        unsigned msk = 0;
#pragma unroll
        for (int q = 0; q < 8; q++) {
            if (s4[q].x <= thr) msk |= 1u << (q * 4 + 0);
            if (s4[q].y <= thr) msk |= 1u << (q * 4 + 1);
            if (s4[q].z <= thr) msk |= 1u << (q * 4 + 2);
            if (s4[q].w <= thr) msk |= 1u << (q * 4 + 3);
        }
        unsigned lw = __ballot_sync(0xffffffffu, msk != 0);
        unsigned ml = __ballot_sync(0xffffffffu, __popc(msk) > 1);

        int id;
        if (ml == 0 && __popc(lw) == 1) {
            // single in-window candidate == argmin, exact
            int src = __ffs(lw) - 1;
            unsigned m2 = __shfl_sync(0xffffffffu, msk, src);
            int bit = __ffs(m2) - 1;
            id = 4 * src + 128 * (bit >> 2) + (bit & 3);
        } else {
            // reconstruct exact residual in reference op order
            float rr[16];
            const float* zfr = g_zf + (long)n * EDIM;
#pragma unroll
            for (int i = 0; i < 16; i++) rr[i] = zfr[lane + 32 * i];
#pragma unroll 1
            for (int tt = 0; tt < t; tt++) {
                const float* er = emb + (long)idxs[tt] * EDIM;
#pragma unroll
                for (int i = 0; i < 16; i++)
                    rr[i] = __fsub_rn(rr[i], er[lane + 32 * i]);
            }
            // rsq in replicated reference order
            float acc = 0.f;
#pragma unroll
            for (int i = 0; i < 16; i++)
                acc = __fadd_rn(acc, __fmul_rn(rr[i], rr[i]));
#pragma unroll
            for (int off = 16; off; off >>= 1)
                acc = __fadd_rn(acc, __shfl_down_sync(0xffffffffu, acc, off));
            float rsq = __shfl_sync(0xffffffffu, acc, 0);

            unsigned long long bestKey = ~0ULL;
            unsigned mym = msk;
            for (;;) {
                // pick up to 2 candidates this pass; candidate c -> lane c
                int myj = -1;
                int c = 0;
                for (;;) {
                    unsigned ball = __ballot_sync(0xffffffffu, mym != 0);
                    if (!ball || c == 2) break;
                    int src = __ffs(ball) - 1;
                    unsigned sm = __shfl_sync(0xffffffffu, mym, src);
                    int b = __ffs(sm) - 1;
                    if (lane == src) mym &= mym - 1;
                    int j = 4 * src + 128 * (b >> 2) + (b & 3);
                    if (lane == c) myj = j;
                    c++;
                }
                if (c == 0) break;
                // stage c rows coalesced into padded smem
                for (int cc = 0; cc < c; cc++) {
                    int j = __shfl_sync(0xffffffffu, myj, cc);
                    const float4* ej4 = (const float4*)(emb + (long)j * EDIM);
                    float* dst = s_stage[wid][cc];
#pragma unroll
                    for (int q = 0; q < 4; q++) {
                        float4 v = ej4[lane + 32 * q];
                        float* d = dst + 4 * (lane + 32 * q);
                        d[0] = v.x; d[1] = v.y; d[2] = v.z; d[3] = v.w;
                    }
                }
                __syncwarp();
                int cc = lane < c ? lane : (c - 1);
                const float* st = s_stage[wid][cc];
                int jj = __shfl_sync(0xffffffffu, myj, cc);
                // exact sequential-k chain: shfl rr broadcast + LDS (bank-free)
                float a2 = 0.f;
#pragma unroll 1
                for (int i = 0; i < 16; i++) {
                    const float* sk = st + 32 * i;
#pragma unroll
                    for (int s = 0; s < 32; s++)
                        a2 = __fmaf_rn(__shfl_sync(0xffffffffu, rr[i], s),
                                       sk[s], a2);
                }
                float dex = __fsub_rn(__fadd_rn(rsq, g_esq[jj]),
                                      __fadd_rn(a2, a2));
                unsigned long long key = (lane < c)
                    ? (((unsigned long long)__float_as_uint(dex) << 32) | (unsigned)jj)
                    : ~0ULL;
#pragma unroll
                for (int off = 16; off; off >>= 1) {
                    unsigned long long o = __shfl_xor_sync(0xffffffffu, key, off);
                    if (o < key) key = o;
                }
                if (key < bestKey) bestKey = key;
                __syncwarp();
                if (c < 2) break;                      // all candidates done
            }
            id = (int)(unsigned)(bestKey & 0xffffffffULL);
        }
        idxs[t] = id;

        if (t < VQ_DEPTH - 1) {
            const float4* g24 = (const float4*)(g_G2 + (long)id * NE);
#pragma unroll
            for (int q = 0; q < 8; q++) {
                float4 g = g24[lane + 32 * q];
                s4[q].x = __fadd_rn(s4[q].x, g.x);
                s4[q].y = __fadd_rn(s4[q].y, g.y);
                s4[q].z = __fadd_rn(s4[q].z, g.z);
                s4[q].w = __fadd_rn(s4[q].w, g.w);
            }
        }
    }

#pragma unroll
    for (int t = 0; t < VQ_DEPTH; t++)
        if (lane == t) out[33554433 + t * N_ROWS + n] = (float)idxs[t];

    // fold + straight-through + loss partial
    int b = n >> 14, hb = (n >> 7) & 127, wb = n & 127;
    const float4* zf4 = (const float4*)(g_zf + (long)n * EDIM);
    float lp = 0.f;
#pragma unroll
    for (int q = 0; q < 4; q++) {
        int p = lane + 32 * q;
        float4 zf = zf4[p];
        float4 zq = make_float4(0.f, 0.f, 0.f, 0.f);
#pragma unroll
        for (int t = 0; t < VQ_DEPTH; t++) {
            const float4* er4 = (const float4*)(emb + (long)idxs[t] * EDIM);
            float4 e = er4[p];
            zq.x = __fadd_rn(zq.x, e.x); zq.y = __fadd_rn(zq.y, e.y);
            zq.z = __fadd_rn(zq.z, e.z); zq.w = __fadd_rn(zq.w, e.w);
        }
        float4 st;
        st.x = __fadd_rn(zf.x, __fsub_rn(zq.x, zf.x));
        st.y = __fadd_rn(zf.y, __fsub_rn(zq.y, zf.y));
        st.z = __fadd_rn(zf.z, __fsub_rn(zq.z, zf.z));
        st.w = __fadd_rn(zf.w, __fsub_rn(zq.w, zf.w));
        long base = (((long)((b << 7) + p)) << 16) + ((hb << 1) << 8) + (wb << 1);
        *(float2*)(out + base)       = make_float2(st.x, st.y);
        *(float2*)(out + base + 256) = make_float2(st.z, st.w);
        float d0 = __fsub_rn(zq.x, zf.x), d1 = __fsub_rn(zq.y, zf.y);
        float d2 = __fsub_rn(zq.z, zf.z), d3 = __fsub_rn(zq.w, zf.w);
        lp = __fadd_rn(lp, __fmul_rn(d0, d0));
        lp = __fadd_rn(lp, __fmul_rn(d1, d1));
        lp = __fadd_rn(lp, __fmul_rn(d2, d2));
        lp = __fadd_rn(lp, __fmul_rn(d3, d3));
    }
#pragma unroll
    for (int off = 16; off; off >>= 1)
        lp += __shfl_xor_sync(0xffffffffu, lp, off);
    if (lane == 0) g_partial[n] = lp;
}

// ---------------------------------------------------------------------------
__global__ void loss_kernel(float* __restrict__ out) {
    __shared__ float sm[256];
    int tid = threadIdx.x;
    float acc = 0.f;
    for (int i = tid; i < N_ROWS; i += 256) acc += g_partial[i];
    sm[tid] = acc;
    __syncthreads();
    for (int off = 128; off; off >>= 1) {
        if (tid < off) sm[tid] += sm[tid + off];
        __syncthreads();
    }
    if (tid == 0) {
        float m = sm[0] / 33554432.0f;
        out[33554432] = __fadd_rn(m, 0.25f * m);
    }
}

// ---------------------------------------------------------------------------
extern "C" void kernel_launch(void* const* d_in, const int* in_sizes, int n_in,
                              void* d_out, int out_size) {
    const float* x   = (const float*)d_in[0];
    const float* emb = (const float*)d_in[1];
    float* out = (float*)d_out;

    unfold_kernel<<<65536, 128>>>(x);
    emb_prep_kernel<<<448, 256>>>(emb);             // gram + esq + emb_h fused
    { dim3 g(8, 512); gemm_u_mma<<<g, 256>>>(); }
    vq_kernel<<<16384, 128>>>(emb, out);            // 4th launch = ncu capture slot
    loss_kernel<<<1, 256>>>(out);
}

// round 15
// speedup vs baseline: 1.0650x; 1.0650x over previous
#include <cuda_runtime.h>
#include <cuda_fp16.h>

#define N_ROWS 65536
#define EDIM 512
#define NE 1024
#define VQ_DEPTH 6
#define MARGIN 2.5e-4f

// Scratch (static __device__ globals: allocation-free per harness rules)
__device__ float g_zf[(size_t)N_ROWS * EDIM];            // 128 MB unfolded (fp32, exact)
__device__ __half g_zf_h[(size_t)N_ROWS * EDIM];         // 64 MB  fp16 copy for MMA
__device__ __half g_emb_h[NE * EDIM];                    // 1 MB
__device__ float g_u[(size_t)N_ROWS * NE];               // 256 MB u0 = 2 r.e (approx ok)
__device__ float g_G2[NE * NE];                          // 4 MB   2 E E^T (approx ok)
__device__ float g_esq[NE];
__device__ int   g_idx[VQ_DEPTH * N_ROWS];               // chosen indices (int)
__device__ float g_partial[4096];                        // per-fold-block loss partials

// ---------------------------------------------------------------------------
// unfold: zf[n][d] = x[b][c][2hb+ki][2wb+kj]; also emit fp16 copy for MMA.
// ---------------------------------------------------------------------------
__global__ void unfold_kernel(const float* __restrict__ x) {
    int bid = blockIdx.x;
    int b = bid >> 14, c = (bid >> 7) & 127, hb = bid & 127;
    int wb = threadIdx.x;
    const float* xr = x + (((long)((b << 7) + c)) << 16) + ((long)(hb << 1) << 8);
    float2 r0 = *(const float2*)(xr + wb * 2);
    float2 r1 = *(const float2*)(xr + 256 + wb * 2);
    long n = ((long)((b << 7) + hb) << 7) + wb;
    float4 v; v.x = r0.x; v.y = r0.y; v.z = r1.x; v.w = r1.y;
    *(float4*)(g_zf + n * EDIM + c * 4) = v;
    __half2 p0, p1;
    p0.x = __float2half_rn(v.x); p0.y = __float2half_rn(v.y);
    p1.x = __float2half_rn(v.z); p1.y = __float2half_rn(v.w);
    *(__half2*)(g_zf_h + n * EDIM + c * 4)     = p0;
    *(__half2*)(g_zf_h + n * EDIM + c * 4 + 2) = p1;
}

// ---------------------------------------------------------------------------
// emb_prep: fused gram (blocks 0..255) + esq (blocks 256..383) +
// emb->fp16 (blocks 384..447).
// ---------------------------------------------------------------------------
__global__ __launch_bounds__(256) void emb_prep_kernel(const float* __restrict__ emb) {
    __shared__ float As[16][64];
    __shared__ float Bs[16][64];
    int blk = blockIdx.x;
    int tid = threadIdx.x;

    if (blk < 256) {
        int row0 = (blk >> 4) * 64;
        int col0 = (blk & 15) * 64;
        int tx = tid & 15, ty = tid >> 4;
        float acc[4][4];
#pragma unroll
        for (int i = 0; i < 4; i++)
#pragma unroll
            for (int j = 0; j < 4; j++) acc[i][j] = 0.f;
        const float* Ab = emb + (long)row0 * 512;
        const float* Bb = emb + (long)col0 * 512;
        int r0 = tid >> 2, c4 = tid & 3;
        for (int k0 = 0; k0 < 512; k0 += 16) {
            float4 va = *(const float4*)(Ab + (long)r0 * 512 + k0 + c4 * 4);
            As[c4 * 4 + 0][r0] = va.x; As[c4 * 4 + 1][r0] = va.y;
            As[c4 * 4 + 2][r0] = va.z; As[c4 * 4 + 3][r0] = va.w;
            float4 vb = *(const float4*)(Bb + (long)r0 * 512 + k0 + c4 * 4);
            Bs[c4 * 4 + 0][r0] = vb.x; Bs[c4 * 4 + 1][r0] = vb.y;
            Bs[c4 * 4 + 2][r0] = vb.z; Bs[c4 * 4 + 3][r0] = vb.w;
            __syncthreads();
#pragma unroll
            for (int kk = 0; kk < 16; kk++) {
                float ra[4], rb[4];
                *(float4*)ra = *(const float4*)&As[kk][ty * 4];
                *(float4*)rb = *(const float4*)&Bs[kk][tx * 4];
#pragma unroll
                for (int i = 0; i < 4; i++)
#pragma unroll
                    for (int j = 0; j < 4; j++) acc[i][j] += ra[i] * rb[j];
            }
            __syncthreads();
        }
#pragma unroll
        for (int i = 0; i < 4; i++) {
            long r = row0 + ty * 4 + i;
            float4 v;
            v.x = 2.f * acc[i][0]; v.y = 2.f * acc[i][1];
            v.z = 2.f * acc[i][2]; v.w = 2.f * acc[i][3];
            *(float4*)(g_G2 + r * NE + col0 + tx * 4) = v;
        }
    } else if (blk < 384) {
        int w = (blk - 256) * 8 + (tid >> 5);
        int lane = tid & 31;
        const float* e = emb + (long)w * EDIM;
        float acc = 0.f;
        for (int i = lane; i < EDIM; i += 32)
            acc = __fadd_rn(acc, __fmul_rn(e[i], e[i]));
        for (int off = 16; off; off >>= 1)
            acc = __fadd_rn(acc, __shfl_down_sync(0xffffffffu, acc, off));
        if (lane == 0) g_esq[w] = acc;
    } else {
        for (int i = (blk - 384) * 256 + tid; i < NE * EDIM; i += 64 * 256)
            g_emb_h[i] = __float2half_rn(emb[i]);
    }
}

// ---------------------------------------------------------------------------
// Tensor-core GEMM (fp16 operands, fp32 accum): g_u = 2 * zf_h @ emb_h^T.
// Tile 128x128x32, 4-stage cp.async.
// ---------------------------------------------------------------------------
#define SMSTRIDE 40

__device__ __forceinline__ unsigned smaddr(const void* p) {
    return (unsigned)__cvta_generic_to_shared(p);
}
#define CP16(dst, src) \
    asm volatile("cp.async.cg.shared.global [%0], [%1], 16;" :: "r"(dst), "l"(src))

__device__ __forceinline__ void mma16816(float* c, const unsigned* a,
                                         unsigned b0, unsigned b1) {
    asm volatile(
        "mma.sync.aligned.m16n8k16.row.col.f32.f16.f16.f32 "
        "{%0,%1,%2,%3}, {%4,%5,%6,%7}, {%8,%9}, {%0,%1,%2,%3};"
        : "+f"(c[0]), "+f"(c[1]), "+f"(c[2]), "+f"(c[3])
        : "r"(a[0]), "r"(a[1]), "r"(a[2]), "r"(a[3]), "r"(b0), "r"(b1));
}

__global__ __launch_bounds__(256) void gemm_u_mma(void) {
    __shared__ __half sA[4][128 * SMSTRIDE];
    __shared__ __half sB[4][128 * SMSTRIDE];
    int tid = threadIdx.x;
    int wid = tid >> 5, lane = tid & 31;
    int warp_m = wid & 3, warp_n = wid >> 2;
    long row0 = (long)blockIdx.y * 128;
    int  col0 = blockIdx.x * 128;

    const __half* Ag = g_zf_h + row0 * 512;
    const __half* Bg = g_emb_h + (long)col0 * 512;

    int lrow = tid >> 2, lchk = tid & 3;

    float acc[2][8][4];
#pragma unroll
    for (int i = 0; i < 2; i++)
#pragma unroll
        for (int j = 0; j < 8; j++)
#pragma unroll
            for (int q = 0; q < 4; q++) acc[i][j][q] = 0.f;

#define STAGE_LOAD(st, k0)                                                      \
    {                                                                           \
        _Pragma("unroll")                                                       \
        for (int h = 0; h < 2; h++) {                                           \
            int r = lrow + h * 64;                                              \
            CP16(smaddr(&sA[st][r * SMSTRIDE + lchk * 8]),                      \
                 Ag + (long)r * 512 + (k0) + lchk * 8);                         \
            CP16(smaddr(&sB[st][r * SMSTRIDE + lchk * 8]),                      \
                 Bg + (long)r * 512 + (k0) + lchk * 8);                         \
        }                                                                       \
        asm volatile("cp.async.commit_group;");                                 \
    }

    STAGE_LOAD(0, 0);
    STAGE_LOAD(1, 32);
    STAGE_LOAD(2, 64);

    int lr8 = (lane & 7) + ((lane >> 3) & 1) * 8;
    int lc8 = ((lane >> 4) & 1) * 8;

#pragma unroll 1
    for (int it = 0; it < 16; it++) {
        asm volatile("cp.async.wait_group 2;" ::: "memory");
        __syncthreads();
        if (it + 3 < 16) STAGE_LOAD((it + 3) & 3, (it + 3) * 32);
        int st = it & 3;
#pragma unroll
        for (int ks = 0; ks < 2; ks++) {
            unsigned a[2][4];
#pragma unroll
            for (int mt = 0; mt < 2; mt++) {
                unsigned ad = smaddr(&sA[st][(warp_m * 32 + mt * 16 + lr8) * SMSTRIDE
                                             + ks * 16 + lc8]);
                asm volatile("ldmatrix.sync.aligned.m8n8.x4.shared.b16 "
                             "{%0,%1,%2,%3}, [%4];"
                             : "=r"(a[mt][0]), "=r"(a[mt][1]),
                               "=r"(a[mt][2]), "=r"(a[mt][3]) : "r"(ad));
            }
#pragma unroll
            for (int g = 0; g < 4; g++) {
                unsigned r0, r1, r2, r3;
                unsigned bd = smaddr(&sB[st][(warp_n * 64 + g * 16 + lr8) * SMSTRIDE
                                             + ks * 16 + lc8]);
                asm volatile("ldmatrix.sync.aligned.m8n8.x4.shared.b16 "
                             "{%0,%1,%2,%3}, [%4];"
                             : "=r"(r0), "=r"(r1), "=r"(r2), "=r"(r3) : "r"(bd));
#pragma unroll
                for (int mt = 0; mt < 2; mt++) {
                    mma16816(acc[mt][g * 2 + 0], a[mt], r0, r2);
                    mma16816(acc[mt][g * 2 + 1], a[mt], r1, r3);
                }
            }
        }
    }

#pragma unroll
    for (int mt = 0; mt < 2; mt++) {
#pragma unroll
        for (int nt = 0; nt < 8; nt++) {
            long m = row0 + warp_m * 32 + mt * 16 + (lane >> 2);
            int  n = col0 + warp_n * 64 + nt * 8 + (lane & 3) * 2;
            float2 v0, v1;
            v0.x = 2.f * acc[mt][nt][0]; v0.y = 2.f * acc[mt][nt][1];
            v1.x = 2.f * acc[mt][nt][2]; v1.y = 2.f * acc[mt][nt][3];
            *(float2*)(g_u + m * NE + n)       = v0;
            *(float2*)(g_u + (m + 8) * NE + n) = v1;
        }
    }
}

// ---------------------------------------------------------------------------
// VQ: indices ONLY (fold/loss moved to fold_kernel). One warp per row,
// deterministic. Fast path: s_j = esq_j - u_j register-resident; min via
// redux.sync; census via ballots. Refine (rare): candidates staged into
// padded smem with coalesced loads; exact sequential-k FFMA chains.
// ---------------------------------------------------------------------------
__global__ __launch_bounds__(128, 8) void vq_kernel(const float* __restrict__ emb,
                                                    float* __restrict__ out) {
    __shared__ float s_stage[4][2][513];
    int wid = threadIdx.x >> 5, lane = threadIdx.x & 31;
    int n = blockIdx.x * 4 + wid;

    float4 s4[8];
    {
        const float4* gu4 = (const float4*)(g_u + (long)n * NE);
        const float4* ge4 = (const float4*)g_esq;
#pragma unroll
        for (int q = 0; q < 8; q++) {
            float4 u = gu4[lane + 32 * q];
            float4 e = ge4[lane + 32 * q];
            s4[q].x = __fsub_rn(e.x, u.x);
            s4[q].y = __fsub_rn(e.y, u.y);
            s4[q].z = __fsub_rn(e.z, u.z);
            s4[q].w = __fsub_rn(e.w, u.w);
        }
    }

    int idxs[VQ_DEPTH];
#pragma unroll 1
    for (int t = 0; t < VQ_DEPTH; t++) {
        float m01, m23, mloc = 3.4e38f;
#pragma unroll
        for (int q = 0; q < 8; q++) {
            m01 = fminf(s4[q].x, s4[q].y);
            m23 = fminf(s4[q].z, s4[q].w);
            mloc = fminf(mloc, fminf(m01, m23));
        }
        unsigned k = __float_as_uint(mloc);
        k = k ^ (unsigned)(((int)k >> 31) | 0x80000000);
        unsigned km;
        asm("redux.sync.min.u32 %0, %1, 0xffffffff;" : "=r"(km) : "r"(k));
        unsigned ub = (km & 0x80000000u) ? (km ^ 0x80000000u) : ~km;
        float thr = __uint_as_float(ub) + MARGIN;

        unsigned msk = 0;
#pragma unroll
        for (int q = 0; q < 8; q++) {
            if (s4[q].x <= thr) msk |= 1u << (q * 4 + 0);
            if (s4[q].y <= thr) msk |= 1u << (q * 4 + 1);
            if (s4[q].z <= thr) msk |= 1u << (q * 4 + 2);
            if (s4[q].w <= thr) msk |= 1u << (q * 4 + 3);
        }
        unsigned lw = __ballot_sync(0xffffffffu, msk != 0);
        unsigned ml = __ballot_sync(0xffffffffu, __popc(msk) > 1);

        int id;
        if (ml == 0 && __popc(lw) == 1) {
            int src = __ffs(lw) - 1;
            unsigned m2 = __shfl_sync(0xffffffffu, msk, src);
            int bit = __ffs(m2) - 1;
            id = 4 * src + 128 * (bit >> 2) + (bit & 3);
        } else {
            // reconstruct exact residual in reference op order
            float rr[16];
            const float* zfr = g_zf + (long)n * EDIM;
#pragma unroll
            for (int i = 0; i < 16; i++) rr[i] = zfr[lane + 32 * i];
#pragma unroll 1
            for (int tt = 0; tt < t; tt++) {
                const float* er = emb + (long)idxs[tt] * EDIM;
#pragma unroll
                for (int i = 0; i < 16; i++)
                    rr[i] = __fsub_rn(rr[i], er[lane + 32 * i]);
            }
            float acc = 0.f;
#pragma unroll
            for (int i = 0; i < 16; i++)
                acc = __fadd_rn(acc, __fmul_rn(rr[i], rr[i]));
#pragma unroll
            for (int off = 16; off; off >>= 1)
                acc = __fadd_rn(acc, __shfl_down_sync(0xffffffffu, acc, off));
            float rsq = __shfl_sync(0xffffffffu, acc, 0);

            unsigned long long bestKey = ~0ULL;
            unsigned mym = msk;
            for (;;) {
                int myj = -1;
                int c = 0;
                for (;;) {
                    unsigned ball = __ballot_sync(0xffffffffu, mym != 0);
                    if (!ball || c == 2) break;
                    int src = __ffs(ball) - 1;
                    unsigned sm = __shfl_sync(0xffffffffu, mym, src);
                    int b = __ffs(sm) - 1;
                    if (lane == src) mym &= mym - 1;
                    int j = 4 * src + 128 * (b >> 2) + (b & 3);
                    if (lane == c) myj = j;
                    c++;
                }
                if (c == 0) break;
                for (int cc = 0; cc < c; cc++) {
                    int j = __shfl_sync(0xffffffffu, myj, cc);
                    const float4* ej4 = (const float4*)(emb + (long)j * EDIM);
                    float* dst = s_stage[wid][cc];
#pragma unroll
                    for (int q = 0; q < 4; q++) {
                        float4 v = ej4[lane + 32 * q];
                        float* d = dst + 4 * (lane + 32 * q);
                        d[0] = v.x; d[1] = v.y; d[2] = v.z; d[3] = v.w;
                    }
                }
                __syncwarp();
                int cc = lane < c ? lane : (c - 1);
                const float* st = s_stage[wid][cc];
                int jj = __shfl_sync(0xffffffffu, myj, cc);
                float a2 = 0.f;
#pragma unroll 1
                for (int i = 0; i < 16; i++) {
                    const float* sk = st + 32 * i;
#pragma unroll
                    for (int s = 0; s < 32; s++)
                        a2 = __fmaf_rn(__shfl_sync(0xffffffffu, rr[i], s),
                                       sk[s], a2);
                }
                float dex = __fsub_rn(__fadd_rn(rsq, g_esq[jj]),
                                      __fadd_rn(a2, a2));
                unsigned long long key = (lane < c)
                    ? (((unsigned long long)__float_as_uint(dex) << 32) | (unsigned)jj)
                    : ~0ULL;
#pragma unroll
                for (int off = 16; off; off >>= 1) {
                    unsigned long long o = __shfl_xor_sync(0xffffffffu, key, off);
                    if (o < key) key = o;
                }
                if (key < bestKey) bestKey = key;
                __syncwarp();
                if (c < 2) break;
            }
            id = (int)(unsigned)(bestKey & 0xffffffffULL);
        }
        idxs[t] = id;

        if (t < VQ_DEPTH - 1) {
            const float4* g24 = (const float4*)(g_G2 + (long)id * NE);
#pragma unroll
            for (int q = 0; q < 8; q++) {
                float4 g = g24[lane + 32 * q];
                s4[q].x = __fadd_rn(s4[q].x, g.x);
                s4[q].y = __fadd_rn(s4[q].y, g.y);
                s4[q].z = __fadd_rn(s4[q].z, g.z);
                s4[q].w = __fadd_rn(s4[q].w, g.w);
            }
        }
    }

#pragma unroll
    for (int t = 0; t < VQ_DEPTH; t++)
        if (lane == t) {
            out[33554433 + t * N_ROWS + n] = (float)idxs[t];
            g_idx[t * N_ROWS + n] = idxs[t];
        }
}

// ---------------------------------------------------------------------------
// fold: 16 rows per block (same b,hb; consecutive wb). Phase 1: warp-per-row
// zq_st into padded smem tile (coalesced emb/zf reads, identical fp op order
// as before). Phase 2: coalesced 128B output stores per (c,ki) segment.
// Loss partial per block via fixed smem tree (deterministic).
// ---------------------------------------------------------------------------
#define FOLD_STRIDE 516

__global__ __launch_bounds__(128) void fold_kernel(const float* __restrict__ emb,
                                                   float* __restrict__ out) {
    __shared__ float sm[16 * FOLD_STRIDE];
    __shared__ float red[128];
    int tid = threadIdx.x, wid = tid >> 5, lane = tid & 31;
    int n0 = blockIdx.x * 16;
    int b = n0 >> 14, hb = (n0 >> 7) & 127, wb0 = n0 & 127;

    float lp = 0.f;
#pragma unroll 1
    for (int i = 0; i < 4; i++) {
        int nl = wid * 4 + i;
        long n = n0 + nl;
        int idx[VQ_DEPTH];
#pragma unroll
        for (int t = 0; t < VQ_DEPTH; t++) idx[t] = g_idx[t * N_ROWS + n];
        const float4* zf4 = (const float4*)(g_zf + n * EDIM);
#pragma unroll
        for (int q = 0; q < 4; q++) {
            int p = lane + 32 * q;
            float4 zf = zf4[p];
            float4 zq = make_float4(0.f, 0.f, 0.f, 0.f);
#pragma unroll
            for (int t = 0; t < VQ_DEPTH; t++) {
                float4 e = ((const float4*)(emb + (long)idx[t] * EDIM))[p];
                zq.x = __fadd_rn(zq.x, e.x); zq.y = __fadd_rn(zq.y, e.y);
                zq.z = __fadd_rn(zq.z, e.z); zq.w = __fadd_rn(zq.w, e.w);
            }
            float4 st;
            st.x = __fadd_rn(zf.x, __fsub_rn(zq.x, zf.x));
            st.y = __fadd_rn(zf.y, __fsub_rn(zq.y, zf.y));
            st.z = __fadd_rn(zf.z, __fsub_rn(zq.z, zf.z));
            st.w = __fadd_rn(zf.w, __fsub_rn(zq.w, zf.w));
            *(float4*)(sm + nl * FOLD_STRIDE + 4 * p) = st;
            float d0 = __fsub_rn(zq.x, zf.x), d1 = __fsub_rn(zq.y, zf.y);
            float d2 = __fsub_rn(zq.z, zf.z), d3 = __fsub_rn(zq.w, zf.w);
            lp = __fadd_rn(lp, __fmul_rn(d0, d0));
            lp = __fadd_rn(lp, __fmul_rn(d1, d1));
            lp = __fadd_rn(lp, __fmul_rn(d2, d2));
            lp = __fadd_rn(lp, __fmul_rn(d3, d3));
        }
    }
    red[tid] = lp;
    __syncthreads();
    for (int off = 64; off; off >>= 1) {
        if (tid < off) red[tid] += red[tid + off];
        __syncthreads();
    }
    if (tid == 0) g_partial[blockIdx.x] = red[0];

    // Phase 2: 256 segments (c,ki); warp handles seg = s*4 + wid.
    // lane -> (wb_local = lane>>1, kj = lane&1): 32 consecutive w floats.
    int wl = lane >> 1, kj = lane & 1;
#pragma unroll 1
    for (int s = 0; s < 64; s++) {
        int seg = s * 4 + wid;
        int c = seg >> 1, ki = seg & 1;
        float v = sm[wl * FOLD_STRIDE + c * 4 + ki * 2 + kj];
        long o = ((((long)((b << 7) + c)) << 8) + (hb * 2 + ki)) * 256
                 + 2 * wb0 + lane;
        out[o] = v;
    }
}

// ---------------------------------------------------------------------------
__global__ void loss_kernel(float* __restrict__ out) {
    __shared__ float sm[256];
    int tid = threadIdx.x;
    float acc = 0.f;
    for (int i = tid; i < 4096; i += 256) acc += g_partial[i];
    sm[tid] = acc;
    __syncthreads();
    for (int off = 128; off; off >>= 1) {
        if (tid < off) sm[tid] += sm[tid + off];
        __syncthreads();
    }
    if (tid == 0) {
        float m = sm[0] / 33554432.0f;
        out[33554432] = __fadd_rn(m, 0.25f * m);
    }
}

// ---------------------------------------------------------------------------
extern "C" void kernel_launch(void* const* d_in, const int* in_sizes, int n_in,
                              void* d_out, int out_size) {
    const float* x   = (const float*)d_in[0];
    const float* emb = (const float*)d_in[1];
    float* out = (float*)d_out;

    unfold_kernel<<<65536, 128>>>(x);
    emb_prep_kernel<<<448, 256>>>(emb);             // gram + esq + emb_h fused
    { dim3 g(8, 512); gemm_u_mma<<<g, 256>>>(); }
    vq_kernel<<<16384, 128>>>(emb, out);            // 4th launch = ncu capture slot
    fold_kernel<<<4096, 128>>>(emb, out);
    loss_kernel<<<1, 256>>>(out);
}

// round 16
// speedup vs baseline: 1.0869x; 1.0206x over previous
#include <cuda_runtime.h>
#include <cuda_fp16.h>

#define N_ROWS 65536
#define EDIM 512
#define NE 1024
#define VQ_DEPTH 6
#define MARGIN 2.5e-4f

// Scratch (static __device__ globals: allocation-free per harness rules)
__device__ float g_zf[(size_t)N_ROWS * EDIM];            // 128 MB unfolded (fp32, exact)
__device__ __half g_zf_h[(size_t)N_ROWS * EDIM];         // 64 MB  fp16 copy for MMA
__device__ __half g_emb_h[NE * EDIM];                    // 1 MB
__device__ float g_u[(size_t)N_ROWS * NE];               // 256 MB u0 = 2 r.e (approx ok)
__device__ __half g_G2h[NE * NE];                        // 2 MB   2 E E^T in fp16 (approx)
__device__ float g_esq[NE];
__device__ int   g_idx[VQ_DEPTH * N_ROWS];               // chosen indices (int)
__device__ float g_partial[4096];                        // per-fold-block loss partials

// ---------------------------------------------------------------------------
// unfold: zf[n][d] = x[b][c][2hb+ki][2wb+kj]; also emit fp16 copy for MMA.
// ---------------------------------------------------------------------------
__global__ void unfold_kernel(const float* __restrict__ x) {
    int bid = blockIdx.x;
    int b = bid >> 14, c = (bid >> 7) & 127, hb = bid & 127;
    int wb = threadIdx.x;
    const float* xr = x + (((long)((b << 7) + c)) << 16) + ((long)(hb << 1) << 8);
    float2 r0 = *(const float2*)(xr + wb * 2);
    float2 r1 = *(const float2*)(xr + 256 + wb * 2);
    long n = ((long)((b << 7) + hb) << 7) + wb;
    float4 v; v.x = r0.x; v.y = r0.y; v.z = r1.x; v.w = r1.y;
    *(float4*)(g_zf + n * EDIM + c * 4) = v;
    __half2 p0, p1;
    p0.x = __float2half_rn(v.x); p0.y = __float2half_rn(v.y);
    p1.x = __float2half_rn(v.z); p1.y = __float2half_rn(v.w);
    *(__half2*)(g_zf_h + n * EDIM + c * 4)     = p0;
    *(__half2*)(g_zf_h + n * EDIM + c * 4 + 2) = p1;
}

// ---------------------------------------------------------------------------
// emb_prep: fused gram->fp16 (blocks 0..255) + esq (256..383) + emb->fp16
// (384..447).
// ---------------------------------------------------------------------------
__global__ __launch_bounds__(256) void emb_prep_kernel(const float* __restrict__ emb) {
    __shared__ float As[16][64];
    __shared__ float Bs[16][64];
    int blk = blockIdx.x;
    int tid = threadIdx.x;

    if (blk < 256) {
        int row0 = (blk >> 4) * 64;
        int col0 = (blk & 15) * 64;
        int tx = tid & 15, ty = tid >> 4;
        float acc[4][4];
#pragma unroll
        for (int i = 0; i < 4; i++)
#pragma unroll
            for (int j = 0; j < 4; j++) acc[i][j] = 0.f;
        const float* Ab = emb + (long)row0 * 512;
        const float* Bb = emb + (long)col0 * 512;
        int r0 = tid >> 2, c4 = tid & 3;
        for (int k0 = 0; k0 < 512; k0 += 16) {
            float4 va = *(const float4*)(Ab + (long)r0 * 512 + k0 + c4 * 4);
            As[c4 * 4 + 0][r0] = va.x; As[c4 * 4 + 1][r0] = va.y;
            As[c4 * 4 + 2][r0] = va.z; As[c4 * 4 + 3][r0] = va.w;
            float4 vb = *(const float4*)(Bb + (long)r0 * 512 + k0 + c4 * 4);
            Bs[c4 * 4 + 0][r0] = vb.x; Bs[c4 * 4 + 1][r0] = vb.y;
            Bs[c4 * 4 + 2][r0] = vb.z; Bs[c4 * 4 + 3][r0] = vb.w;
            __syncthreads();
#pragma unroll
            for (int kk = 0; kk < 16; kk++) {
                float ra[4], rb[4];
                *(float4*)ra = *(const float4*)&As[kk][ty * 4];
                *(float4*)rb = *(const float4*)&Bs[kk][tx * 4];
#pragma unroll
                for (int i = 0; i < 4; i++)
#pragma unroll
                    for (int j = 0; j < 4; j++) acc[i][j] += ra[i] * rb[j];
            }
            __syncthreads();
        }
#pragma unroll
        for (int i = 0; i < 4; i++) {
            long r = row0 + ty * 4 + i;
            __half2 h0 = __floats2half2_rn(2.f * acc[i][0], 2.f * acc[i][1]);
            __half2 h1 = __floats2half2_rn(2.f * acc[i][2], 2.f * acc[i][3]);
            uint2 pk;
            pk.x = *(unsigned*)&h0;
            pk.y = *(unsigned*)&h1;
            *(uint2*)(g_G2h + r * NE + col0 + tx * 4) = pk;
        }
    } else if (blk < 384) {
        int w = (blk - 256) * 8 + (tid >> 5);
        int lane = tid & 31;
        const float* e = emb + (long)w * EDIM;
        float acc = 0.f;
        for (int i = lane; i < EDIM; i += 32)
            acc = __fadd_rn(acc, __fmul_rn(e[i], e[i]));
        for (int off = 16; off; off >>= 1)
            acc = __fadd_rn(acc, __shfl_down_sync(0xffffffffu, acc, off));
        if (lane == 0) g_esq[w] = acc;
    } else {
        for (int i = (blk - 384) * 256 + tid; i < NE * EDIM; i += 64 * 256)
            g_emb_h[i] = __float2half_rn(emb[i]);
    }
}

// ---------------------------------------------------------------------------
// Tensor-core GEMM (fp16 operands, fp32 accum): g_u = 2 * zf_h @ emb_h^T.
// Tile 128x128x32, 4-stage cp.async.
// ---------------------------------------------------------------------------
#define SMSTRIDE 40

__device__ __forceinline__ unsigned smaddr(const void* p) {
    return (unsigned)__cvta_generic_to_shared(p);
}
#define CP16(dst, src) \
    asm volatile("cp.async.cg.shared.global [%0], [%1], 16;" :: "r"(dst), "l"(src))

__device__ __forceinline__ void mma16816(float* c, const unsigned* a,
                                         unsigned b0, unsigned b1) {
    asm volatile(
        "mma.sync.aligned.m16n8k16.row.col.f32.f16.f16.f32 "
        "{%0,%1,%2,%3}, {%4,%5,%6,%7}, {%8,%9}, {%0,%1,%2,%3};"
        : "+f"(c[0]), "+f"(c[1]), "+f"(c[2]), "+f"(c[3])
        : "r"(a[0]), "r"(a[1]), "r"(a[2]), "r"(a[3]), "r"(b0), "r"(b1));
}

__global__ __launch_bounds__(256) void gemm_u_mma(void) {
    __shared__ __half sA[4][128 * SMSTRIDE];
    __shared__ __half sB[4][128 * SMSTRIDE];
    int tid = threadIdx.x;
    int wid = tid >> 5, lane = tid & 31;
    int warp_m = wid & 3, warp_n = wid >> 2;
    long row0 = (long)blockIdx.y * 128;
    int  col0 = blockIdx.x * 128;

    const __half* Ag = g_zf_h + row0 * 512;
    const __half* Bg = g_emb_h + (long)col0 * 512;

    int lrow = tid >> 2, lchk = tid & 3;

    float acc[2][8][4];
#pragma unroll
    for (int i = 0; i < 2; i++)
#pragma unroll
        for (int j = 0; j < 8; j++)
#pragma unroll
            for (int q = 0; q < 4; q++) acc[i][j][q] = 0.f;

#define STAGE_LOAD(st, k0)                                                      \
    {                                                                           \
        _Pragma("unroll")                                                       \
        for (int h = 0; h < 2; h++) {                                           \
            int r = lrow + h * 64;                                              \
            CP16(smaddr(&sA[st][r * SMSTRIDE + lchk * 8]),                      \
                 Ag + (long)r * 512 + (k0) + lchk * 8);                         \
            CP16(smaddr(&sB[st][r * SMSTRIDE + lchk * 8]),                      \
                 Bg + (long)r * 512 + (k0) + lchk * 8);                         \
        }                                                                       \
        asm volatile("cp.async.commit_group;");                                 \
    }

    STAGE_LOAD(0, 0);
    STAGE_LOAD(1, 32);
    STAGE_LOAD(2, 64);

    int lr8 = (lane & 7) + ((lane >> 3) & 1) * 8;
    int lc8 = ((lane >> 4) & 1) * 8;

#pragma unroll 1
    for (int it = 0; it < 16; it++) {
        asm volatile("cp.async.wait_group 2;" ::: "memory");
        __syncthreads();
        if (it + 3 < 16) STAGE_LOAD((it + 3) & 3, (it + 3) * 32);
        int st = it & 3;
#pragma unroll
        for (int ks = 0; ks < 2; ks++) {
            unsigned a[2][4];
#pragma unroll
            for (int mt = 0; mt < 2; mt++) {
                unsigned ad = smaddr(&sA[st][(warp_m * 32 + mt * 16 + lr8) * SMSTRIDE
                                             + ks * 16 + lc8]);
                asm volatile("ldmatrix.sync.aligned.m8n8.x4.shared.b16 "
                             "{%0,%1,%2,%3}, [%4];"
                             : "=r"(a[mt][0]), "=r"(a[mt][1]),
                               "=r"(a[mt][2]), "=r"(a[mt][3]) : "r"(ad));
            }
#pragma unroll
            for (int g = 0; g < 4; g++) {
                unsigned r0, r1, r2, r3;
                unsigned bd = smaddr(&sB[st][(warp_n * 64 + g * 16 + lr8) * SMSTRIDE
                                             + ks * 16 + lc8]);
                asm volatile("ldmatrix.sync.aligned.m8n8.x4.shared.b16 "
                             "{%0,%1,%2,%3}, [%4];"
                             : "=r"(r0), "=r"(r1), "=r"(r2), "=r"(r3) : "r"(bd));
#pragma unroll
                for (int mt = 0; mt < 2; mt++) {
                    mma16816(acc[mt][g * 2 + 0], a[mt], r0, r2);
                    mma16816(acc[mt][g * 2 + 1], a[mt], r1, r3);
                }
            }
        }
    }

#pragma unroll
    for (int mt = 0; mt < 2; mt++) {
#pragma unroll
        for (int nt = 0; nt < 8; nt++) {
            long m = row0 + warp_m * 32 + mt * 16 + (lane >> 2);
            int  n = col0 + warp_n * 64 + nt * 8 + (lane & 3) * 2;
            float2 v0, v1;
            v0.x = 2.f * acc[mt][nt][0]; v0.y = 2.f * acc[mt][nt][1];
            v1.x = 2.f * acc[mt][nt][2]; v1.y = 2.f * acc[mt][nt][3];
            *(float2*)(g_u + m * NE + n)       = v0;
            *(float2*)(g_u + (m + 8) * NE + n) = v1;
        }
    }
}

// ---------------------------------------------------------------------------
// VQ: indices only. One warp per row, deterministic.
// Fast path: s_j = esq_j - u_j register-resident; per depth s += G2h[id]
// (fp16 row -> halved L2 traffic; error ~1e-6 << MARGIN). Min via redux.sync;
// census via ballots. Refine (rare): exact fp32 chains, reference op order.
// ---------------------------------------------------------------------------
__global__ __launch_bounds__(128, 8) void vq_kernel(const float* __restrict__ emb,
                                                    float* __restrict__ out) {
    __shared__ float s_stage[4][2][513];
    int wid = threadIdx.x >> 5, lane = threadIdx.x & 31;
    int n = blockIdx.x * 4 + wid;

    float4 s4[8];
    {
        const float4* gu4 = (const float4*)(g_u + (long)n * NE);
        const float4* ge4 = (const float4*)g_esq;
#pragma unroll
        for (int q = 0; q < 8; q++) {
            float4 u = gu4[lane + 32 * q];
            float4 e = ge4[lane + 32 * q];
            s4[q].x = __fsub_rn(e.x, u.x);
            s4[q].y = __fsub_rn(e.y, u.y);
            s4[q].z = __fsub_rn(e.z, u.z);
            s4[q].w = __fsub_rn(e.w, u.w);
        }
    }

    int idxs[VQ_DEPTH];
#pragma unroll 1
    for (int t = 0; t < VQ_DEPTH; t++) {
        float m01, m23, mloc = 3.4e38f;
#pragma unroll
        for (int q = 0; q < 8; q++) {
            m01 = fminf(s4[q].x, s4[q].y);
            m23 = fminf(s4[q].z, s4[q].w);
            mloc = fminf(mloc, fminf(m01, m23));
        }
        unsigned k = __float_as_uint(mloc);
        k = k ^ (unsigned)(((int)k >> 31) | 0x80000000);
        unsigned km;
        asm("redux.sync.min.u32 %0, %1, 0xffffffff;" : "=r"(km) : "r"(k));
        unsigned ub = (km & 0x80000000u) ? (km ^ 0x80000000u) : ~km;
        float thr = __uint_as_float(ub) + MARGIN;

        unsigned msk = 0;
#pragma unroll
        for (int q = 0; q < 8; q++) {
            if (s4[q].x <= thr) msk |= 1u << (q * 4 + 0);
            if (s4[q].y <= thr) msk |= 1u << (q * 4 + 1);
            if (s4[q].z <= thr) msk |= 1u << (q * 4 + 2);
            if (s4[q].w <= thr) msk |= 1u << (q * 4 + 3);
        }
        unsigned lw = __ballot_sync(0xffffffffu, msk != 0);
        unsigned ml = __ballot_sync(0xffffffffu, __popc(msk) > 1);

        int id;
        if (ml == 0 && __popc(lw) == 1) {
            int src = __ffs(lw) - 1;
            unsigned m2 = __shfl_sync(0xffffffffu, msk, src);
            int bit = __ffs(m2) - 1;
            id = 4 * src + 128 * (bit >> 2) + (bit & 3);
        } else {
            // reconstruct exact residual in reference op order
            float rr[16];
            const float* zfr = g_zf + (long)n * EDIM;
#pragma unroll
            for (int i = 0; i < 16; i++) rr[i] = zfr[lane + 32 * i];
#pragma unroll 1
            for (int tt = 0; tt < t; tt++) {
                const float* er = emb + (long)idxs[tt] * EDIM;
#pragma unroll
                for (int i = 0; i < 16; i++)
                    rr[i] = __fsub_rn(rr[i], er[lane + 32 * i]);
            }
            float acc = 0.f;
#pragma unroll
            for (int i = 0; i < 16; i++)
                acc = __fadd_rn(acc, __fmul_rn(rr[i], rr[i]));
#pragma unroll
            for (int off = 16; off; off >>= 1)
                acc = __fadd_rn(acc, __shfl_down_sync(0xffffffffu, acc, off));
            float rsq = __shfl_sync(0xffffffffu, acc, 0);

            unsigned long long bestKey = ~0ULL;
            unsigned mym = msk;
            for (;;) {
                int myj = -1;
                int c = 0;
                for (;;) {
                    unsigned ball = __ballot_sync(0xffffffffu, mym != 0);
                    if (!ball || c == 2) break;
                    int src = __ffs(ball) - 1;
                    unsigned sm = __shfl_sync(0xffffffffu, mym, src);
                    int b = __ffs(sm) - 1;
                    if (lane == src) mym &= mym - 1;
                    int j = 4 * src + 128 * (b >> 2) + (b & 3);
                    if (lane == c) myj = j;
                    c++;
                }
                if (c == 0) break;
                for (int cc = 0; cc < c; cc++) {
                    int j = __shfl_sync(0xffffffffu, myj, cc);
                    const float4* ej4 = (const float4*)(emb + (long)j * EDIM);
                    float* dst = s_stage[wid][cc];
#pragma unroll
                    for (int q = 0; q < 4; q++) {
                        float4 v = ej4[lane + 32 * q];
                        float* d = dst + 4 * (lane + 32 * q);
                        d[0] = v.x; d[1] = v.y; d[2] = v.z; d[3] = v.w;
                    }
                }
                __syncwarp();
                int cc = lane < c ? lane : (c - 1);
                const float* st = s_stage[wid][cc];
                int jj = __shfl_sync(0xffffffffu, myj, cc);
                float a2 = 0.f;
#pragma unroll 1
                for (int i = 0; i < 16; i++) {
                    const float* sk = st + 32 * i;
#pragma unroll
                    for (int s = 0; s < 32; s++)
                        a2 = __fmaf_rn(__shfl_sync(0xffffffffu, rr[i], s),
                                       sk[s], a2);
                }
                float dex = __fsub_rn(__fadd_rn(rsq, g_esq[jj]),
                                      __fadd_rn(a2, a2));
                unsigned long long key = (lane < c)
                    ? (((unsigned long long)__float_as_uint(dex) << 32) | (unsigned)jj)
                    : ~0ULL;
#pragma unroll
                for (int off = 16; off; off >>= 1) {
                    unsigned long long o = __shfl_xor_sync(0xffffffffu, key, off);
                    if (o < key) key = o;
                }
                if (key < bestKey) bestKey = key;
                __syncwarp();
                if (c < 2) break;
            }
            id = (int)(unsigned)(bestKey & 0xffffffffULL);
        }
        idxs[t] = id;

        if (t < VQ_DEPTH - 1) {
            // fp16 G2 row: 4 halves per lane-group via one uint2 (8B) load
            const uint2* g2p = (const uint2*)(g_G2h + (long)id * NE);
#pragma unroll
            for (int q = 0; q < 8; q++) {
                uint2 pk = g2p[lane + 32 * q];
                float2 a = __half22float2(*(__half2*)&pk.x);
                float2 b = __half22float2(*(__half2*)&pk.y);
                s4[q].x = __fadd_rn(s4[q].x, a.x);
                s4[q].y = __fadd_rn(s4[q].y, a.y);
                s4[q].z = __fadd_rn(s4[q].z, b.x);
                s4[q].w = __fadd_rn(s4[q].w, b.y);
            }
        }
    }

#pragma unroll
    for (int t = 0; t < VQ_DEPTH; t++)
        if (lane == t) {
            out[33554433 + t * N_ROWS + n] = (float)idxs[t];
            g_idx[t * N_ROWS + n] = idxs[t];
        }
}

// ---------------------------------------------------------------------------
// fold: 16 rows per block. Phase 1: warp-per-row zq_st into padded smem tile
// (coalesced reads, identical fp op order). Phase 2: coalesced 128B stores.
// ---------------------------------------------------------------------------
#define FOLD_STRIDE 516

__global__ __launch_bounds__(128) void fold_kernel(const float* __restrict__ emb,
                                                   float* __restrict__ out) {
    __shared__ float sm[16 * FOLD_STRIDE];
    __shared__ float red[128];
    int tid = threadIdx.x, wid = tid >> 5, lane = tid & 31;
    int n0 = blockIdx.x * 16;
    int b = n0 >> 14, hb = (n0 >> 7) & 127, wb0 = n0 & 127;

    float lp = 0.f;
#pragma unroll 1
    for (int i = 0; i < 4; i++) {
        int nl = wid * 4 + i;
        long n = n0 + nl;
        int idx[VQ_DEPTH];
#pragma unroll
        for (int t = 0; t < VQ_DEPTH; t++) idx[t] = g_idx[t * N_ROWS + n];
        const float4* zf4 = (const float4*)(g_zf + n * EDIM);
#pragma unroll
        for (int q = 0; q < 4; q++) {
            int p = lane + 32 * q;
            float4 zf = zf4[p];
            float4 zq = make_float4(0.f, 0.f, 0.f, 0.f);
#pragma unroll
            for (int t = 0; t < VQ_DEPTH; t++) {
                float4 e = ((const float4*)(emb + (long)idx[t] * EDIM))[p];
                zq.x = __fadd_rn(zq.x, e.x); zq.y = __fadd_rn(zq.y, e.y);
                zq.z = __fadd_rn(zq.z, e.z); zq.w = __fadd_rn(zq.w, e.w);
            }
            float4 st;
            st.x = __fadd_rn(zf.x, __fsub_rn(zq.x, zf.x));
            st.y = __fadd_rn(zf.y, __fsub_rn(zq.y, zf.y));
            st.z = __fadd_rn(zf.z, __fsub_rn(zq.z, zf.z));
            st.w = __fadd_rn(zf.w, __fsub_rn(zq.w, zf.w));
            *(float4*)(sm + nl * FOLD_STRIDE + 4 * p) = st;
            float d0 = __fsub_rn(zq.x, zf.x), d1 = __fsub_rn(zq.y, zf.y);
            float d2 = __fsub_rn(zq.z, zf.z), d3 = __fsub_rn(zq.w, zf.w);
            lp = __fadd_rn(lp, __fmul_rn(d0, d0));
            lp = __fadd_rn(lp, __fmul_rn(d1, d1));
            lp = __fadd_rn(lp, __fmul_rn(d2, d2));
            lp = __fadd_rn(lp, __fmul_rn(d3, d3));
        }
    }
    red[tid] = lp;
    __syncthreads();
    for (int off = 64; off; off >>= 1) {
        if (tid < off) red[tid] += red[tid + off];
        __syncthreads();
    }
    if (tid == 0) g_partial[blockIdx.x] = red[0];

    int wl = lane >> 1, kj = lane & 1;
#pragma unroll 1
    for (int s = 0; s < 64; s++) {
        int seg = s * 4 + wid;
        int c = seg >> 1, ki = seg & 1;
        float v = sm[wl * FOLD_STRIDE + c * 4 + ki * 2 + kj];
        long o = ((((long)((b << 7) + c)) << 8) + (hb * 2 + ki)) * 256
                 + 2 * wb0 + lane;
        out[o] = v;
    }
}

// ---------------------------------------------------------------------------
__global__ void loss_kernel(float* __restrict__ out) {
    __shared__ float sm[256];
    int tid = threadIdx.x;
    float acc = 0.f;
    for (int i = tid; i < 4096; i += 256) acc += g_partial[i];
    sm[tid] = acc;
    __syncthreads();
    for (int off = 128; off; off >>= 1) {
        if (tid < off) sm[tid] += sm[tid + off];
        __syncthreads();
    }
    if (tid == 0) {
        float m = sm[0] / 33554432.0f;
        out[33554432] = __fadd_rn(m, 0.25f * m);
    }
}

// ---------------------------------------------------------------------------
extern "C" void kernel_launch(void* const* d_in, const int* in_sizes, int n_in,
                              void* d_out, int out_size) {
    const float* x   = (const float*)d_in[0];
    const float* emb = (const float*)d_in[1];
    float* out = (float*)d_out;

    unfold_kernel<<<65536, 128>>>(x);
    emb_prep_kernel<<<448, 256>>>(emb);             // gram(fp16) + esq + emb_h fused
    { dim3 g(8, 512); gemm_u_mma<<<g, 256>>>(); }
    vq_kernel<<<16384, 128>>>(emb, out);            // 4th launch = ncu capture slot
    fold_kernel<<<4096, 128>>>(emb, out);
    loss_kernel<<<1, 256>>>(out);
}

// round 17
// speedup vs baseline: 1.1053x; 1.0169x over previous
#include <cuda_runtime.h>
#include <cuda_fp16.h>

#define N_ROWS 65536
#define EDIM 512
#define NE 1024
#define VQ_DEPTH 6
#define MARGIN 2.5e-4f

// Scratch (static __device__ globals: allocation-free per harness rules)
__device__ float g_zf[(size_t)N_ROWS * EDIM];            // 128 MB unfolded (fp32, exact)
__device__ __half g_zf_h[(size_t)N_ROWS * EDIM];         // 64 MB  fp16 copy for MMA
__device__ __half g_emb_h[NE * EDIM];                    // 1 MB
__device__ float g_u[(size_t)N_ROWS * NE];               // 256 MB u0 = 2 r.e (approx ok)
__device__ __half g_G2h[NE * NE];                        // 2 MB   2 E E^T in fp16 (approx)
__device__ float g_esq[NE];
__device__ int   g_idx[VQ_DEPTH * N_ROWS];               // chosen indices (int)
__device__ float g_partial[4096];                        // per-fold-block loss partials

#define TILE_STRIDE 516

// ---------------------------------------------------------------------------
// unfold v2: smem-transposed (mirror of fold). Block = (b, hb, 16-wb group).
// Phase 1: coalesced 128B reads of x per (c,ki) segment into padded tile.
// Phase 2: coalesced float4 zf writes + half2 zf_h writes.
// ---------------------------------------------------------------------------
__global__ __launch_bounds__(128) void unfold_kernel(const float* __restrict__ x) {
    __shared__ float sm[16 * TILE_STRIDE];
    int tid = threadIdx.x, wid = tid >> 5, lane = tid & 31;
    int bid = blockIdx.x;                     // ((b*128)+hb)*8 + wbg
    int wbg = bid & 7;
    int hb = (bid >> 3) & 127;
    int b = bid >> 10;
    long n0 = ((long)((b << 7) + hb) << 7) + wbg * 16;

    // Phase 1: 256 segments (c,ki); warp handles seg = s*4+wid.
    int wl = lane >> 1, kj = lane & 1;
#pragma unroll 1
    for (int s = 0; s < 64; s++) {
        int seg = s * 4 + wid;
        int c = seg >> 1, ki = seg & 1;
        const float* xr = x + (((long)((b << 7) + c)) << 16)
                            + ((long)((hb << 1) + ki) << 8) + wbg * 32;
        float v = xr[lane];
        sm[wl * TILE_STRIDE + c * 4 + ki * 2 + kj] = v;
    }
    __syncthreads();

    // Phase 2: 4 rows per warp, coalesced writes.
#pragma unroll
    for (int i = 0; i < 4; i++) {
        int nl = wid * 4 + i;
        long n = n0 + nl;
#pragma unroll
        for (int q = 0; q < 4; q++) {
            int p = lane + 32 * q;
            float4 v = *(float4*)(sm + nl * TILE_STRIDE + 4 * p);
            *(float4*)(g_zf + n * EDIM + 4 * p) = v;
            __half2 h0, h1;
            h0.x = __float2half_rn(v.x); h0.y = __float2half_rn(v.y);
            h1.x = __float2half_rn(v.z); h1.y = __float2half_rn(v.w);
            uint2 pk;
            pk.x = *(unsigned*)&h0; pk.y = *(unsigned*)&h1;
            *(uint2*)(g_zf_h + n * EDIM + 4 * p) = pk;
        }
    }
}

// ---------------------------------------------------------------------------
// emb_prep: fused gram->fp16 (blocks 0..255) + esq (256..383) + emb->fp16
// (384..447).
// ---------------------------------------------------------------------------
__global__ __launch_bounds__(256) void emb_prep_kernel(const float* __restrict__ emb) {
    __shared__ float As[16][64];
    __shared__ float Bs[16][64];
    int blk = blockIdx.x;
    int tid = threadIdx.x;

    if (blk < 256) {
        int row0 = (blk >> 4) * 64;
        int col0 = (blk & 15) * 64;
        int tx = tid & 15, ty = tid >> 4;
        float acc[4][4];
#pragma unroll
        for (int i = 0; i < 4; i++)
#pragma unroll
            for (int j = 0; j < 4; j++) acc[i][j] = 0.f;
        const float* Ab = emb + (long)row0 * 512;
        const float* Bb = emb + (long)col0 * 512;
        int r0 = tid >> 2, c4 = tid & 3;
        for (int k0 = 0; k0 < 512; k0 += 16) {
            float4 va = *(const float4*)(Ab + (long)r0 * 512 + k0 + c4 * 4);
            As[c4 * 4 + 0][r0] = va.x; As[c4 * 4 + 1][r0] = va.y;
            As[c4 * 4 + 2][r0] = va.z; As[c4 * 4 + 3][r0] = va.w;
            float4 vb = *(const float4*)(Bb + (long)r0 * 512 + k0 + c4 * 4);
            Bs[c4 * 4 + 0][r0] = vb.x; Bs[c4 * 4 + 1][r0] = vb.y;
            Bs[c4 * 4 + 2][r0] = vb.z; Bs[c4 * 4 + 3][r0] = vb.w;
            __syncthreads();
#pragma unroll
            for (int kk = 0; kk < 16; kk++) {
                float ra[4], rb[4];
                *(float4*)ra = *(const float4*)&As[kk][ty * 4];
                *(float4*)rb = *(const float4*)&Bs[kk][tx * 4];
#pragma unroll
                for (int i = 0; i < 4; i++)
#pragma unroll
                    for (int j = 0; j < 4; j++) acc[i][j] += ra[i] * rb[j];
            }
            __syncthreads();
        }
#pragma unroll
        for (int i = 0; i < 4; i++) {
            long r = row0 + ty * 4 + i;
            __half2 h0 = __floats2half2_rn(2.f * acc[i][0], 2.f * acc[i][1]);
            __half2 h1 = __floats2half2_rn(2.f * acc[i][2], 2.f * acc[i][3]);
            uint2 pk;
            pk.x = *(unsigned*)&h0;
            pk.y = *(unsigned*)&h1;
            *(uint2*)(g_G2h + r * NE + col0 + tx * 4) = pk;
        }
    } else if (blk < 384) {
        int w = (blk - 256) * 8 + (tid >> 5);
        int lane = tid & 31;
        const float* e = emb + (long)w * EDIM;
        float acc = 0.f;
        for (int i = lane; i < EDIM; i += 32)
            acc = __fadd_rn(acc, __fmul_rn(e[i], e[i]));
        for (int off = 16; off; off >>= 1)
            acc = __fadd_rn(acc, __shfl_down_sync(0xffffffffu, acc, off));
        if (lane == 0) g_esq[w] = acc;
    } else {
        for (int i = (blk - 384) * 256 + tid; i < NE * EDIM; i += 64 * 256)
            g_emb_h[i] = __float2half_rn(emb[i]);
    }
}

// ---------------------------------------------------------------------------
// Tensor-core GEMM (fp16 operands, fp32 accum): g_u = 2 * zf_h @ emb_h^T.
// Tile 128x128x32, 4-stage cp.async.
// ---------------------------------------------------------------------------
#define SMSTRIDE 40

__device__ __forceinline__ unsigned smaddr(const void* p) {
    return (unsigned)__cvta_generic_to_shared(p);
}
#define CP16(dst, src) \
    asm volatile("cp.async.cg.shared.global [%0], [%1], 16;" :: "r"(dst), "l"(src))

__device__ __forceinline__ void mma16816(float* c, const unsigned* a,
                                         unsigned b0, unsigned b1) {
    asm volatile(
        "mma.sync.aligned.m16n8k16.row.col.f32.f16.f16.f32 "
        "{%0,%1,%2,%3}, {%4,%5,%6,%7}, {%8,%9}, {%0,%1,%2,%3};"
        : "+f"(c[0]), "+f"(c[1]), "+f"(c[2]), "+f"(c[3])
        : "r"(a[0]), "r"(a[1]), "r"(a[2]), "r"(a[3]), "r"(b0), "r"(b1));
}

__global__ __launch_bounds__(256) void gemm_u_mma(void) {
    __shared__ __half sA[4][128 * SMSTRIDE];
    __shared__ __half sB[4][128 * SMSTRIDE];
    int tid = threadIdx.x;
    int wid = tid >> 5, lane = tid & 31;
    int warp_m = wid & 3, warp_n = wid >> 2;
    long row0 = (long)blockIdx.y * 128;
    int  col0 = blockIdx.x * 128;

    const __half* Ag = g_zf_h + row0 * 512;
    const __half* Bg = g_emb_h + (long)col0 * 512;

    int lrow = tid >> 2, lchk = tid & 3;

    float acc[2][8][4];
#pragma unroll
    for (int i = 0; i < 2; i++)
#pragma unroll
        for (int j = 0; j < 8; j++)
#pragma unroll
            for (int q = 0; q < 4; q++) acc[i][j][q] = 0.f;

#define STAGE_LOAD(st, k0)                                                      \
    {                                                                           \
        _Pragma("unroll")                                                       \
        for (int h = 0; h < 2; h++) {                                           \
            int r = lrow + h * 64;                                              \
            CP16(smaddr(&sA[st][r * SMSTRIDE + lchk * 8]),                      \
                 Ag + (long)r * 512 + (k0) + lchk * 8);                         \
            CP16(smaddr(&sB[st][r * SMSTRIDE + lchk * 8]),                      \
                 Bg + (long)r * 512 + (k0) + lchk * 8);                         \
        }                                                                       \
        asm volatile("cp.async.commit_group;");                                 \
    }

    STAGE_LOAD(0, 0);
    STAGE_LOAD(1, 32);
    STAGE_LOAD(2, 64);

    int lr8 = (lane & 7) + ((lane >> 3) & 1) * 8;
    int lc8 = ((lane >> 4) & 1) * 8;

#pragma unroll 1
    for (int it = 0; it < 16; it++) {
        asm volatile("cp.async.wait_group 2;" ::: "memory");
        __syncthreads();
        if (it + 3 < 16) STAGE_LOAD((it + 3) & 3, (it + 3) * 32);
        int st = it & 3;
#pragma unroll
        for (int ks = 0; ks < 2; ks++) {
            unsigned a[2][4];
#pragma unroll
            for (int mt = 0; mt < 2; mt++) {
                unsigned ad = smaddr(&sA[st][(warp_m * 32 + mt * 16 + lr8) * SMSTRIDE
                                             + ks * 16 + lc8]);
                asm volatile("ldmatrix.sync.aligned.m8n8.x4.shared.b16 "
                             "{%0,%1,%2,%3}, [%4];"
                             : "=r"(a[mt][0]), "=r"(a[mt][1]),
                               "=r"(a[mt][2]), "=r"(a[mt][3]) : "r"(ad));
            }
#pragma unroll
            for (int g = 0; g < 4; g++) {
                unsigned r0, r1, r2, r3;
                unsigned bd = smaddr(&sB[st][(warp_n * 64 + g * 16 + lr8) * SMSTRIDE
                                             + ks * 16 + lc8]);
                asm volatile("ldmatrix.sync.aligned.m8n8.x4.shared.b16 "
                             "{%0,%1,%2,%3}, [%4];"
                             : "=r"(r0), "=r"(r1), "=r"(r2), "=r"(r3) : "r"(bd));
#pragma unroll
                for (int mt = 0; mt < 2; mt++) {
                    mma16816(acc[mt][g * 2 + 0], a[mt], r0, r2);
                    mma16816(acc[mt][g * 2 + 1], a[mt], r1, r3);
                }
            }
        }
    }

#pragma unroll
    for (int mt = 0; mt < 2; mt++) {
#pragma unroll
        for (int nt = 0; nt < 8; nt++) {
            long m = row0 + warp_m * 32 + mt * 16 + (lane >> 2);
            int  n = col0 + warp_n * 64 + nt * 8 + (lane & 3) * 2;
            float2 v0, v1;
            v0.x = 2.f * acc[mt][nt][0]; v0.y = 2.f * acc[mt][nt][1];
            v1.x = 2.f * acc[mt][nt][2]; v1.y = 2.f * acc[mt][nt][3];
            *(float2*)(g_u + m * NE + n)       = v0;
            *(float2*)(g_u + (m + 8) * NE + n) = v1;
        }
    }
}

// ---------------------------------------------------------------------------
// VQ: indices only. One warp per row, deterministic. Block order REVERSED so
// vq consumes the most-recently-written u rows first (L2 reuse of the GEMM
// output tail). Fast path register-resident; refine exact (reference order).
// ---------------------------------------------------------------------------
__global__ __launch_bounds__(128, 8) void vq_kernel(const float* __restrict__ emb,
                                                    float* __restrict__ out) {
    __shared__ float s_stage[4][2][513];
    int wid = threadIdx.x >> 5, lane = threadIdx.x & 31;
    int n = ((16383 - blockIdx.x) << 2) + wid;

    float4 s4[8];
    {
        const float4* gu4 = (const float4*)(g_u + (long)n * NE);
        const float4* ge4 = (const float4*)g_esq;
#pragma unroll
        for (int q = 0; q < 8; q++) {
            float4 u = gu4[lane + 32 * q];
            float4 e = ge4[lane + 32 * q];
            s4[q].x = __fsub_rn(e.x, u.x);
            s4[q].y = __fsub_rn(e.y, u.y);
            s4[q].z = __fsub_rn(e.z, u.z);
            s4[q].w = __fsub_rn(e.w, u.w);
        }
    }

    int idxs[VQ_DEPTH];
#pragma unroll 1
    for (int t = 0; t < VQ_DEPTH; t++) {
        float m01, m23, mloc = 3.4e38f;
#pragma unroll
        for (int q = 0; q < 8; q++) {
            m01 = fminf(s4[q].x, s4[q].y);
            m23 = fminf(s4[q].z, s4[q].w);
            mloc = fminf(mloc, fminf(m01, m23));
        }
        unsigned k = __float_as_uint(mloc);
        k = k ^ (unsigned)(((int)k >> 31) | 0x80000000);
        unsigned km;
        asm("redux.sync.min.u32 %0, %1, 0xffffffff;" : "=r"(km) : "r"(k));
        unsigned ub = (km & 0x80000000u) ? (km ^ 0x80000000u) : ~km;
        float thr = __uint_as_float(ub) + MARGIN;

        unsigned msk = 0;
#pragma unroll
        for (int q = 0; q < 8; q++) {
            if (s4[q].x <= thr) msk |= 1u << (q * 4 + 0);
            if (s4[q].y <= thr) msk |= 1u << (q * 4 + 1);
            if (s4[q].z <= thr) msk |= 1u << (q * 4 + 2);
            if (s4[q].w <= thr) msk |= 1u << (q * 4 + 3);
        }
        unsigned lw = __ballot_sync(0xffffffffu, msk != 0);
        unsigned ml = __ballot_sync(0xffffffffu, __popc(msk) > 1);

        int id;
        if (ml == 0 && __popc(lw) == 1) {
            int src = __ffs(lw) - 1;
            unsigned m2 = __shfl_sync(0xffffffffu, msk, src);
            int bit = __ffs(m2) - 1;
            id = 4 * src + 128 * (bit >> 2) + (bit & 3);
        } else {
            // reconstruct exact residual in reference op order
            float rr[16];
            const float* zfr = g_zf + (long)n * EDIM;
#pragma unroll
            for (int i = 0; i < 16; i++) rr[i] = zfr[lane + 32 * i];
#pragma unroll 1
            for (int tt = 0; tt < t; tt++) {
                const float* er = emb + (long)idxs[tt] * EDIM;
#pragma unroll
                for (int i = 0; i < 16; i++)
                    rr[i] = __fsub_rn(rr[i], er[lane + 32 * i]);
            }
            float acc = 0.f;
#pragma unroll
            for (int i = 0; i < 16; i++)
                acc = __fadd_rn(acc, __fmul_rn(rr[i], rr[i]));
#pragma unroll
            for (int off = 16; off; off >>= 1)
                acc = __fadd_rn(acc, __shfl_down_sync(0xffffffffu, acc, off));
            float rsq = __shfl_sync(0xffffffffu, acc, 0);

            unsigned long long bestKey = ~0ULL;
            unsigned mym = msk;
            for (;;) {
                int myj = -1;
                int c = 0;
                for (;;) {
                    unsigned ball = __ballot_sync(0xffffffffu, mym != 0);
                    if (!ball || c == 2) break;
                    int src = __ffs(ball) - 1;
                    unsigned sm2 = __shfl_sync(0xffffffffu, mym, src);
                    int b = __ffs(sm2) - 1;
                    if (lane == src) mym &= mym - 1;
                    int j = 4 * src + 128 * (b >> 2) + (b & 3);
                    if (lane == c) myj = j;
                    c++;
                }
                if (c == 0) break;
                for (int cc = 0; cc < c; cc++) {
                    int j = __shfl_sync(0xffffffffu, myj, cc);
                    const float4* ej4 = (const float4*)(emb + (long)j * EDIM);
                    float* dst = s_stage[wid][cc];
#pragma unroll
                    for (int q = 0; q < 4; q++) {
                        float4 v = ej4[lane + 32 * q];
                        float* d = dst + 4 * (lane + 32 * q);
                        d[0] = v.x; d[1] = v.y; d[2] = v.z; d[3] = v.w;
                    }
                }
                __syncwarp();
                int cc = lane < c ? lane : (c - 1);
                const float* st = s_stage[wid][cc];
                int jj = __shfl_sync(0xffffffffu, myj, cc);
                float a2 = 0.f;
#pragma unroll 1
                for (int i = 0; i < 16; i++) {
                    const float* sk = st + 32 * i;
#pragma unroll
                    for (int s = 0; s < 32; s++)
                        a2 = __fmaf_rn(__shfl_sync(0xffffffffu, rr[i], s),
                                       sk[s], a2);
                }
                float dex = __fsub_rn(__fadd_rn(rsq, g_esq[jj]),
                                      __fadd_rn(a2, a2));
                unsigned long long key = (lane < c)
                    ? (((unsigned long long)__float_as_uint(dex) << 32) | (unsigned)jj)
                    : ~0ULL;
#pragma unroll
                for (int off = 16; off; off >>= 1) {
                    unsigned long long o = __shfl_xor_sync(0xffffffffu, key, off);
                    if (o < key) key = o;
                }
                if (key < bestKey) bestKey = key;
                __syncwarp();
                if (c < 2) break;
            }
            id = (int)(unsigned)(bestKey & 0xffffffffULL);
        }
        idxs[t] = id;

        if (t < VQ_DEPTH - 1) {
            const uint2* g2p = (const uint2*)(g_G2h + (long)id * NE);
#pragma unroll
            for (int q = 0; q < 8; q++) {
                uint2 pk = g2p[lane + 32 * q];
                float2 a = __half22float2(*(__half2*)&pk.x);
                float2 b = __half22float2(*(__half2*)&pk.y);
                s4[q].x = __fadd_rn(s4[q].x, a.x);
                s4[q].y = __fadd_rn(s4[q].y, a.y);
                s4[q].z = __fadd_rn(s4[q].z, b.x);
                s4[q].w = __fadd_rn(s4[q].w, b.y);
            }
        }
    }

#pragma unroll
    for (int t = 0; t < VQ_DEPTH; t++)
        if (lane == t) {
            out[33554433 + t * N_ROWS + n] = (float)idxs[t];
            g_idx[t * N_ROWS + n] = idxs[t];
        }
}

// ---------------------------------------------------------------------------
// fold: 16 rows per block. Phase 1: warp-per-row zq_st into padded smem tile
// (coalesced reads, identical fp op order). Phase 2: coalesced 128B stores.
// ---------------------------------------------------------------------------
__global__ __launch_bounds__(128) void fold_kernel(const float* __restrict__ emb,
                                                   float* __restrict__ out) {
    __shared__ float sm[16 * TILE_STRIDE];
    __shared__ float red[128];
    int tid = threadIdx.x, wid = tid >> 5, lane = tid & 31;
    int n0 = blockIdx.x * 16;
    int b = n0 >> 14, hb = (n0 >> 7) & 127, wb0 = n0 & 127;

    float lp = 0.f;
#pragma unroll 1
    for (int i = 0; i < 4; i++) {
        int nl = wid * 4 + i;
        long n = n0 + nl;
        int idx[VQ_DEPTH];
#pragma unroll
        for (int t = 0; t < VQ_DEPTH; t++) idx[t] = g_idx[t * N_ROWS + n];
        const float4* zf4 = (const float4*)(g_zf + n * EDIM);
#pragma unroll
        for (int q = 0; q < 4; q++) {
            int p = lane + 32 * q;
            float4 zf = zf4[p];
            float4 zq = make_float4(0.f, 0.f, 0.f, 0.f);
#pragma unroll
            for (int t = 0; t < VQ_DEPTH; t++) {
                float4 e = ((const float4*)(emb + (long)idx[t] * EDIM))[p];
                zq.x = __fadd_rn(zq.x, e.x); zq.y = __fadd_rn(zq.y, e.y);
                zq.z = __fadd_rn(zq.z, e.z); zq.w = __fadd_rn(zq.w, e.w);
            }
            float4 st;
            st.x = __fadd_rn(zf.x, __fsub_rn(zq.x, zf.x));
            st.y = __fadd_rn(zf.y, __fsub_rn(zq.y, zf.y));
            st.z = __fadd_rn(zf.z, __fsub_rn(zq.z, zf.z));
            st.w = __fadd_rn(zf.w, __fsub_rn(zq.w, zf.w));
            *(float4*)(sm + nl * TILE_STRIDE + 4 * p) = st;
            float d0 = __fsub_rn(zq.x, zf.x), d1 = __fsub_rn(zq.y, zf.y);
            float d2 = __fsub_rn(zq.z, zf.z), d3 = __fsub_rn(zq.w, zf.w);
            lp = __fadd_rn(lp, __fmul_rn(d0, d0));
            lp = __fadd_rn(lp, __fmul_rn(d1, d1));
            lp = __fadd_rn(lp, __fmul_rn(d2, d2));
            lp = __fadd_rn(lp, __fmul_rn(d3, d3));
        }
    }
    red[tid] = lp;
    __syncthreads();
    for (int off = 64; off; off >>= 1) {
        if (tid < off) red[tid] += red[tid + off];
        __syncthreads();
    }
    if (tid == 0) g_partial[blockIdx.x] = red[0];

    int wl = lane >> 1, kj = lane & 1;
#pragma unroll 1
    for (int s = 0; s < 64; s++) {
        int seg = s * 4 + wid;
        int c = seg >> 1, ki = seg & 1;
        float v = sm[wl * TILE_STRIDE + c * 4 + ki * 2 + kj];
        long o = ((((long)((b << 7) + c)) << 8) + (hb * 2 + ki)) * 256
                 + 2 * wb0 + lane;
        out[o] = v;
    }
}

// ---------------------------------------------------------------------------
__global__ void loss_kernel(float* __restrict__ out) {
    __shared__ float sm[256];
    int tid = threadIdx.x;
    float acc = 0.f;
    for (int i = tid; i < 4096; i += 256) acc += g_partial[i];
    sm[tid] = acc;
    __syncthreads();
    for (int off = 128; off; off >>= 1) {
        if (tid < off) sm[tid] += sm[tid + off];
        __syncthreads();
    }
    if (tid == 0) {
        float m = sm[0] / 33554432.0f;
        out[33554432] = __fadd_rn(m, 0.25f * m);
    }
}

// ---------------------------------------------------------------------------
extern "C" void kernel_launch(void* const* d_in, const int* in_sizes, int n_in,
                              void* d_out, int out_size) {
    const float* x   = (const float*)d_in[0];
    const float* emb = (const float*)d_in[1];
    float* out = (float*)d_out;

    unfold_kernel<<<4096, 128>>>(x);
    emb_prep_kernel<<<448, 256>>>(emb);             // gram(fp16) + esq + emb_h fused
    { dim3 g(8, 512); gemm_u_mma<<<g, 256>>>(); }
    vq_kernel<<<16384, 128>>>(emb, out);            // 4th launch = ncu capture slot
    fold_kernel<<<4096, 128>>>(emb, out);
    loss_kernel<<<1, 256>>>(out);
}